// round 1
// baseline (speedup 1.0000x reference)
#include <cuda_runtime.h>
#include <math.h>

#define BATCH 2
#define SEQ   2048
#define DM    1024
#define NH    16
#define DH    64

// Scratch (allocation-free rule: __device__ globals)
__device__ float g_Q[BATCH*NH*SEQ*DH];     // [b,h,s,dh], scale 1/8 folded in
__device__ float g_K[BATCH*NH*SEQ*DH];
__device__ float g_V[BATCH*NH*SEQ*DH];
__device__ float g_att[BATCH*SEQ*DM];      // [b,s,d]
__device__ float g_rinv[BATCH*NH*SEQ];     // 1/rowsum per (b,h,q)

// ---------------------------------------------------------------------------
// Projection GEMM: out = (X @ W + bias) * scale
// M=4096, N=1024, K=1024.  64x64 tile, 256 threads, 4x4 microtile, KC=32.
// mode 0/1/2 -> write g_Q/g_K/g_V in [b,h,s,dh] layout; mode 3 -> flat to outp
// mode 3 also reads from g_att instead of X.
// ---------------------------------------------------------------------------
__global__ void proj_kernel(const float* __restrict__ X,
                            const float* __restrict__ W,
                            const float* __restrict__ bias,
                            float* __restrict__ outp,
                            float scale, int mode) {
    __shared__ __align__(16) float XsT[32][68];   // XsT[k][row]
    __shared__ __align__(16) float Ws [32][68];   // Ws[k][n]
    const float* Xp = (mode == 3) ? g_att : X;
    float* out = (mode == 0) ? g_Q : (mode == 1) ? g_K : (mode == 2) ? g_V : outp;

    int tid = threadIdx.x;
    int tx = tid & 15, ty = tid >> 4;
    int n0 = blockIdx.x * 64;
    int m0 = blockIdx.y * 64;

    float acc[4][4] = {};
    for (int k0 = 0; k0 < DM; k0 += 32) {
        #pragma unroll
        for (int e = 0; e < 8; e++) {
            int i = tid + e * 256;
            int row = i >> 5, kk = i & 31;
            XsT[kk][row] = Xp[(size_t)(m0 + row) * DM + k0 + kk];
        }
        #pragma unroll
        for (int e = 0; e < 8; e++) {
            int i = tid + e * 256;
            int kk = i >> 6, nn = i & 63;
            Ws[kk][nn] = W[(size_t)(k0 + kk) * DM + n0 + nn];
        }
        __syncthreads();
        #pragma unroll
        for (int kk = 0; kk < 32; kk++) {
            float4 a4 = *(const float4*)&XsT[kk][ty * 4];
            float4 b4 = *(const float4*)&Ws[kk][tx * 4];
            float av[4] = {a4.x, a4.y, a4.z, a4.w};
            float bv[4] = {b4.x, b4.y, b4.z, b4.w};
            #pragma unroll
            for (int i = 0; i < 4; i++)
                #pragma unroll
                for (int j = 0; j < 4; j++)
                    acc[i][j] += av[i] * bv[j];
        }
        __syncthreads();
    }

    float4 bb4 = *(const float4*)&bias[n0 + tx * 4];
    float bb[4] = {bb4.x, bb4.y, bb4.z, bb4.w};
    #pragma unroll
    for (int i = 0; i < 4; i++) {
        int m = m0 + ty * 4 + i;
        float4 o;
        o.x = (acc[i][0] + bb[0]) * scale;
        o.y = (acc[i][1] + bb[1]) * scale;
        o.z = (acc[i][2] + bb[2]) * scale;
        o.w = (acc[i][3] + bb[3]) * scale;
        if (mode != 3) {
            int b = m >> 11, s = m & (SEQ - 1);
            int n = n0 + tx * 4;
            int h = n >> 6, d = n & 63;
            *(float4*)&out[(size_t)(((b * NH + h) * SEQ) + s) * DH + d] = o;
        } else {
            *(float4*)&out[(size_t)m * DM + n0 + tx * 4] = o;
        }
    }
}

// ---------------------------------------------------------------------------
// Attention: per (b,h, 64-row q-tile): S = Q·K^T (scale pre-folded),
// E = exp(S) written unnormalized to weights gmem, rowsum accumulated,
// acc += E·V.  Final: attended = acc / rowsum; store 1/rowsum for normalize.
// ---------------------------------------------------------------------------
__global__ void attn_kernel(float* __restrict__ weights) {
    extern __shared__ __align__(16) float smem[];
    float (*QsT)[68] = (float(*)[68])smem;                 // [64][68] Q^T
    float (*KsT)[68] = (float(*)[68])(smem + 64 * 68);     // [64][68] K^T
    float (*Vs )[68] = (float(*)[68])(smem + 2 * 64 * 68); // [64][68] V
    float (*Es )[68] = (float(*)[68])(smem + 3 * 64 * 68); // [64][68] exp(S)

    int tid = threadIdx.x;
    int tx = tid & 15, ty = tid >> 4;
    int bh = blockIdx.y;          // b*NH + h
    int q0 = blockIdx.x * 64;

    const float* Q = g_Q + (size_t)bh * SEQ * DH;
    const float* K = g_K + (size_t)bh * SEQ * DH;
    const float* V = g_V + (size_t)bh * SEQ * DH;
    float* wbh = weights + (size_t)bh * SEQ * SEQ;

    #pragma unroll
    for (int e = 0; e < 16; e++) {
        int i = tid + e * 256;
        int row = i >> 6, d = i & 63;
        QsT[d][row] = Q[(size_t)(q0 + row) * DH + d];
    }

    float acc[4][4] = {};
    float lsum[4] = {};

    for (int kt = 0; kt < SEQ / 64; kt++) {
        #pragma unroll
        for (int e = 0; e < 16; e++) {
            int i = tid + e * 256;
            int row = i >> 6, d = i & 63;
            float kv = K[(size_t)(kt * 64 + row) * DH + d];
            float vv = V[(size_t)(kt * 64 + row) * DH + d];
            KsT[d][row] = kv;
            Vs[row][d]  = vv;
        }
        __syncthreads();

        float s[4][4] = {};
        #pragma unroll
        for (int d = 0; d < 64; d++) {
            float4 a4 = *(const float4*)&QsT[d][ty * 4];
            float4 b4 = *(const float4*)&KsT[d][tx * 4];
            float av[4] = {a4.x, a4.y, a4.z, a4.w};
            float bv[4] = {b4.x, b4.y, b4.z, b4.w};
            #pragma unroll
            for (int i = 0; i < 4; i++)
                #pragma unroll
                for (int j = 0; j < 4; j++)
                    s[i][j] += av[i] * bv[j];
        }

        #pragma unroll
        for (int i = 0; i < 4; i++) {
            float4 e4;
            e4.x = __expf(s[i][0]);
            e4.y = __expf(s[i][1]);
            e4.z = __expf(s[i][2]);
            e4.w = __expf(s[i][3]);
            lsum[i] += (e4.x + e4.y) + (e4.z + e4.w);
            *(float4*)&Es[ty * 4 + i][tx * 4] = e4;
            *(float4*)&wbh[(size_t)(q0 + ty * 4 + i) * SEQ + kt * 64 + tx * 4] = e4;
        }
        __syncthreads();

        #pragma unroll
        for (int k = 0; k < 64; k++) {
            float4 b4 = *(const float4*)&Vs[k][tx * 4];
            float bv[4] = {b4.x, b4.y, b4.z, b4.w};
            float av[4];
            av[0] = Es[ty * 4 + 0][k];
            av[1] = Es[ty * 4 + 1][k];
            av[2] = Es[ty * 4 + 2][k];
            av[3] = Es[ty * 4 + 3][k];
            #pragma unroll
            for (int i = 0; i < 4; i++)
                #pragma unroll
                for (int j = 0; j < 4; j++)
                    acc[i][j] += av[i] * bv[j];
        }
        __syncthreads();
    }

    // Reduce rowsums across tx (reuse Es)
    #pragma unroll
    for (int i = 0; i < 4; i++) Es[ty * 4 + i][tx] = lsum[i];
    __syncthreads();

    float rinv[4];
    #pragma unroll
    for (int i = 0; i < 4; i++) {
        float t = 0.f;
        #pragma unroll
        for (int u = 0; u < 16; u++) t += Es[ty * 4 + i][u];
        rinv[i] = 1.0f / t;
        if (tx == 0) g_rinv[bh * SEQ + q0 + ty * 4 + i] = rinv[i];
    }

    int b = bh >> 4, h = bh & 15;
    #pragma unroll
    for (int i = 0; i < 4; i++) {
        float4 o;
        o.x = acc[i][0] * rinv[i];
        o.y = acc[i][1] * rinv[i];
        o.z = acc[i][2] * rinv[i];
        o.w = acc[i][3] * rinv[i];
        *(float4*)&g_att[(size_t)(b * SEQ + q0 + ty * 4 + i) * DM + h * DH + tx * 4] = o;
    }
}

// ---------------------------------------------------------------------------
// Normalize weights in place: w[b,h,q,:] *= g_rinv[b,h,q]
// ---------------------------------------------------------------------------
__global__ void norm_kernel(float* __restrict__ w) {
    size_t f4 = (size_t)blockIdx.x * blockDim.x + threadIdx.x;
    size_t fidx = f4 * 4;                      // float index
    int row = (int)(fidx >> 11);               // /SEQ
    float r = g_rinv[row];
    float4 v = *(float4*)&w[fidx];
    v.x *= r; v.y *= r; v.z *= r; v.w *= r;
    *(float4*)&w[fidx] = v;
}

// ---------------------------------------------------------------------------
extern "C" void kernel_launch(void* const* d_in, const int* in_sizes, int n_in,
                              void* d_out, int out_size) {
    const float* x  = (const float*)d_in[0];
    const float* wq = (const float*)d_in[1];
    const float* bq = (const float*)d_in[2];
    const float* wk = (const float*)d_in[3];
    const float* bk = (const float*)d_in[4];
    const float* wv = (const float*)d_in[5];
    const float* bv = (const float*)d_in[6];
    const float* wo = (const float*)d_in[7];
    const float* bo = (const float*)d_in[8];

    float* out     = (float*)d_out;                       // [2,2048,1024]
    float* weights = out + (size_t)BATCH * SEQ * DM;      // [2,16,2048,2048]

    const int ATTN_SMEM = 4 * 64 * 68 * sizeof(float);    // 69632 B
    static bool attr_set = false;
    if (!attr_set) {
        cudaFuncSetAttribute(attn_kernel,
                             cudaFuncAttributeMaxDynamicSharedMemorySize, ATTN_SMEM);
        attr_set = true;
    }

    dim3 pg(DM / 64, (BATCH * SEQ) / 64);   // (16, 64)
    const float scale = 0.125f;             // 1/sqrt(DH), folded into Q

    proj_kernel<<<pg, 256>>>(x, wq, bq, nullptr, scale, 0);  // Q (scaled)
    proj_kernel<<<pg, 256>>>(x, wk, bk, nullptr, 1.0f, 1);   // K
    proj_kernel<<<pg, 256>>>(x, wv, bv, nullptr, 1.0f, 2);   // V

    attn_kernel<<<dim3(SEQ / 64, BATCH * NH), 256, ATTN_SMEM>>>(weights);

    size_t nf4 = (size_t)BATCH * NH * SEQ * SEQ / 4;         // 33,554,432
    norm_kernel<<<(unsigned)(nf4 / 256), 256>>>(weights);

    proj_kernel<<<pg, 256>>>(nullptr, wo, bo, out, 1.0f, 3); // out projection
}

// round 3
// speedup vs baseline: 4.0370x; 4.0370x over previous
#include <cuda_runtime.h>
#include <cuda_bf16.h>
#include <cstdint>

#define BATCH 2
#define SEQ   2048
#define DM    1024
#define NH    16
#define DH    64
#define M_TOT (BATCH*SEQ)   // 4096
#define BH_TOT (BATCH*NH)   // 32

// ---------------------------------------------------------------------------
// Scratch (__device__ globals; allocation-free rule)
// ---------------------------------------------------------------------------
__device__ __nv_bfloat16 g_xH[M_TOT*DM],  g_xL[M_TOT*DM];
__device__ __nv_bfloat16 g_WtH[3*DM*DM],  g_WtL[3*DM*DM];      // [n][k], q|k|v
__device__ __nv_bfloat16 g_WoTH[DM*DM],   g_WoTL[DM*DM];       // [n][k]
__device__ __nv_bfloat16 g_QH[BH_TOT*SEQ*DH], g_QL[BH_TOT*SEQ*DH];
__device__ __nv_bfloat16 g_KH[BH_TOT*SEQ*DH], g_KL[BH_TOT*SEQ*DH];
__device__ __nv_bfloat16 g_VtH[BH_TOT*DH*SEQ], g_VtL[BH_TOT*DH*SEQ]; // [bh][d][s]
__device__ __nv_bfloat16 g_attH[M_TOT*DM], g_attL[M_TOT*DM];
__device__ float g_rinv[BH_TOT*SEQ];

// ---------------------------------------------------------------------------
// Helpers (arch-portable: ldmatrix + mma.sync, valid on compute_103)
// ---------------------------------------------------------------------------
__device__ __forceinline__ uint32_t smem_u32(const void* p) {
    uint32_t a;
    asm("{ .reg .u64 t; cvta.to.shared.u64 t, %1; cvt.u32.u64 %0, t; }" : "=r"(a) : "l"(p));
    return a;
}
__device__ __forceinline__ void ldsm4(uint32_t* r, uint32_t a) {
    asm volatile("ldmatrix.sync.aligned.m8n8.x4.shared.b16 {%0,%1,%2,%3}, [%4];"
        : "=r"(r[0]), "=r"(r[1]), "=r"(r[2]), "=r"(r[3]) : "r"(a));
}
__device__ __forceinline__ void mma16816(float* d, const uint32_t* a, const uint32_t* b) {
    asm volatile("mma.sync.aligned.m16n8k16.row.col.f32.bf16.bf16.f32 "
        "{%0,%1,%2,%3},{%4,%5,%6,%7},{%8,%9},{%0,%1,%2,%3};"
        : "+f"(d[0]), "+f"(d[1]), "+f"(d[2]), "+f"(d[3])
        : "r"(a[0]), "r"(a[1]), "r"(a[2]), "r"(a[3]), "r"(b[0]), "r"(b[1]));
}
__device__ __forceinline__ void split2(float v, __nv_bfloat16& h, __nv_bfloat16& l) {
    h = __float2bfloat16(v);
    l = __float2bfloat16(v - __bfloat162float(h));
}
__device__ __forceinline__ uint32_t pack2(__nv_bfloat16 a, __nv_bfloat16 b) {
    __nv_bfloat162 t; t.x = a; t.y = b;
    return *reinterpret_cast<uint32_t*>(&t);
}

// ---------------------------------------------------------------------------
// Prep: split x, transpose+split weights
// ---------------------------------------------------------------------------
__global__ void split_x_kernel(const float* __restrict__ x) {
    size_t i4 = (size_t)blockIdx.x * blockDim.x + threadIdx.x;
    float4 v = *(const float4*)&x[i4 * 4];
    __nv_bfloat16 h[4], l[4];
    split2(v.x, h[0], l[0]); split2(v.y, h[1], l[1]);
    split2(v.z, h[2], l[2]); split2(v.w, h[3], l[3]);
    *(uint2*)&g_xH[i4 * 4] = *(uint2*)h;
    *(uint2*)&g_xL[i4 * 4] = *(uint2*)l;
}

__global__ void tsplit_kernel(const float* __restrict__ W, int which) {
    __shared__ float t[32][33];
    __nv_bfloat16* H = (which < 3) ? g_WtH + (size_t)which * DM * DM : g_WoTH;
    __nv_bfloat16* L = (which < 3) ? g_WtL + (size_t)which * DM * DM : g_WoTL;
    int x0 = blockIdx.x * 32, y0 = blockIdx.y * 32;
    int tx = threadIdx.x, ty = threadIdx.y;
    #pragma unroll
    for (int r = 0; r < 4; r++)
        t[ty + r * 8][tx] = W[(size_t)(y0 + ty + r * 8) * DM + x0 + tx];
    __syncthreads();
    #pragma unroll
    for (int r = 0; r < 4; r++) {
        float v = t[tx][ty + r * 8];
        __nv_bfloat16 h, l; split2(v, h, l);
        size_t dst = (size_t)(x0 + ty + r * 8) * DM + y0 + tx;
        H[dst] = h; L[dst] = l;
    }
}

// ---------------------------------------------------------------------------
// Projection GEMM mainloop: C(128x128) = A[m0..][1024] x B[n0..][1024]^T
// 3-pass split bf16 via mma.sync. 256 thr = 8 warps (4m x 2n), warp 32x64.
// smem tiles pitch 72 bf16 (144B): conflict-free ldmatrix (banks 4r).
// ---------------------------------------------------------------------------
#define PS_AH 0
#define PS_AL 18432
#define PS_BH 36864
#define PS_BL 55296
#define PROJ_SMEM 73728

__device__ __forceinline__ void gemm_ml(char* smem,
    const __nv_bfloat16* __restrict__ Ah, const __nv_bfloat16* __restrict__ Al,
    const __nv_bfloat16* __restrict__ Bh, const __nv_bfloat16* __restrict__ Bl,
    int m0, int n0, float (&c)[2][8][4]) {
    uint32_t sb = smem_u32(smem);
    int tid = threadIdx.x, lane = tid & 31, w = tid >> 5;
    int wm = (w >> 1) * 32, wn = (w & 1) * 64;

    for (int k0 = 0; k0 < DM; k0 += 64) {
        __syncthreads();
        #pragma unroll
        for (int e = 0; e < 4; e++) {
            int i = tid + e * 256;
            int row = i >> 3, cc = i & 7;
            size_t ga = (size_t)(m0 + row) * DM + k0 + cc * 8;
            size_t gb = (size_t)(n0 + row) * DM + k0 + cc * 8;
            int so = row * 144 + cc * 16;
            *(uint4*)(smem + PS_AH + so) = *(const uint4*)(Ah + ga);
            *(uint4*)(smem + PS_AL + so) = *(const uint4*)(Al + ga);
            *(uint4*)(smem + PS_BH + so) = *(const uint4*)(Bh + gb);
            *(uint4*)(smem + PS_BL + so) = *(const uint4*)(Bl + gb);
        }
        __syncthreads();
        #pragma unroll
        for (int ks = 0; ks < 64; ks += 16) {
            uint32_t ah[2][4], al[2][4], bhf[8][2], blf[8][2];
            #pragma unroll
            for (int mt = 0; mt < 2; mt++) {
                uint32_t ad = sb + PS_AH + (uint32_t)(wm + mt * 16 + (lane & 15)) * 144
                            + (ks + (lane >> 4) * 8) * 2;
                ldsm4(ah[mt], ad);
                ldsm4(al[mt], ad + (PS_AL - PS_AH));
            }
            #pragma unroll
            for (int nt2 = 0; nt2 < 4; nt2++) {
                uint32_t bd = sb + PS_BH
                            + (uint32_t)(wn + nt2 * 16 + ((lane >> 4) << 3) + (lane & 7)) * 144
                            + (ks + ((lane >> 3) & 1) * 8) * 2;
                uint32_t t[4];
                ldsm4(t, bd);
                bhf[nt2*2][0]=t[0]; bhf[nt2*2][1]=t[1]; bhf[nt2*2+1][0]=t[2]; bhf[nt2*2+1][1]=t[3];
                ldsm4(t, bd + (PS_BL - PS_BH));
                blf[nt2*2][0]=t[0]; blf[nt2*2][1]=t[1]; blf[nt2*2+1][0]=t[2]; blf[nt2*2+1][1]=t[3];
            }
            #pragma unroll
            for (int mt = 0; mt < 2; mt++)
                #pragma unroll
                for (int nt = 0; nt < 8; nt++) {
                    mma16816(c[mt][nt], ah[mt], bhf[nt]);
                    mma16816(c[mt][nt], ah[mt], blf[nt]);
                    mma16816(c[mt][nt], al[mt], bhf[nt]);
                }
        }
    }
}

// ---------------------------------------------------------------------------
// QKV projection
// ---------------------------------------------------------------------------
__global__ void __launch_bounds__(256, 1) proj_qkv_kernel(
    const float* __restrict__ bq, const float* __restrict__ bk, const float* __restrict__ bv) {
    extern __shared__ char smem[];
    int n0 = blockIdx.x * 128;   // 0..2944 (3072 total)
    int m0 = blockIdx.y * 128;
    float c[2][8][4] = {};
    gemm_ml(smem, g_xH, g_xL, g_WtH, g_WtL, m0, n0, c);

    int tid = threadIdx.x, lane = tid & 31, w = tid >> 5;
    int wm = (w >> 1) * 32, wn = (w & 1) * 64;
    int gid = lane >> 2, tid4 = lane & 3;
    int j = n0 >> 10, nb = n0 & 1023;
    const float* bias = (j == 0) ? bq : (j == 1) ? bk : bv;
    float scale = (j == 0) ? 0.125f : 1.0f;
    __nv_bfloat16* dH = (j == 0) ? g_QH : g_KH;
    __nv_bfloat16* dL = (j == 0) ? g_QL : g_KL;

    #pragma unroll
    for (int mt = 0; mt < 2; mt++)
        #pragma unroll
        for (int rh = 0; rh < 2; rh++) {
            int m = m0 + wm + mt * 16 + rh * 8 + gid;
            int b = m >> 11, s2 = m & (SEQ - 1);
            #pragma unroll
            for (int nt = 0; nt < 8; nt++) {
                int nl = nb + wn + nt * 8 + tid4 * 2;
                float v0 = (c[mt][nt][rh * 2 + 0] + bias[nl]) * scale;
                float v1 = (c[mt][nt][rh * 2 + 1] + bias[nl + 1]) * scale;
                __nv_bfloat16 h0, l0, h1, l1;
                split2(v0, h0, l0); split2(v1, h1, l1);
                int hh = nl >> 6, d = nl & 63;
                if (j < 2) {
                    size_t dst = (((size_t)(b * NH + hh)) * SEQ + s2) * DH + d;
                    *(uint32_t*)&dH[dst] = pack2(h0, h1);
                    *(uint32_t*)&dL[dst] = pack2(l0, l1);
                } else {
                    size_t dst = (((size_t)(b * NH + hh)) * DH + d) * SEQ + s2;
                    g_VtH[dst] = h0; g_VtH[dst + SEQ] = h1;
                    g_VtL[dst] = l0; g_VtL[dst + SEQ] = l1;
                }
            }
        }
}

// ---------------------------------------------------------------------------
// Output projection
// ---------------------------------------------------------------------------
__global__ void __launch_bounds__(256, 1) proj_o_kernel(
    const float* __restrict__ bo, float* __restrict__ out) {
    extern __shared__ char smem[];
    int n0 = blockIdx.x * 128;
    int m0 = blockIdx.y * 128;
    float c[2][8][4] = {};
    gemm_ml(smem, g_attH, g_attL, g_WoTH, g_WoTL, m0, n0, c);

    int tid = threadIdx.x, lane = tid & 31, w = tid >> 5;
    int wm = (w >> 1) * 32, wn = (w & 1) * 64;
    int gid = lane >> 2, tid4 = lane & 3;

    #pragma unroll
    for (int mt = 0; mt < 2; mt++)
        #pragma unroll
        for (int rh = 0; rh < 2; rh++) {
            int m = m0 + wm + mt * 16 + rh * 8 + gid;
            #pragma unroll
            for (int nt = 0; nt < 8; nt++) {
                int n = n0 + wn + nt * 8 + tid4 * 2;
                float2 o;
                o.x = c[mt][nt][rh * 2 + 0] + bo[n];
                o.y = c[mt][nt][rh * 2 + 1] + bo[n + 1];
                *(float2*)&out[(size_t)m * DM + n] = o;
            }
        }
}

// ---------------------------------------------------------------------------
// Attention. Per (bh, 128-q tile). S frags in regs -> exp -> weights gmem
// (unnormalized) + E split into smem -> PV mma accumulates in regs over kt.
// ---------------------------------------------------------------------------
#define AS_QH 0
#define AS_QL 18432
#define AS_KH 36864
#define AS_KL 55296
#define AS_VH 73728
#define AS_VL 91136
#define AS_EH 108544
#define AS_EL 143360
#define AS_RED 178176
#define ATTN_SMEM 179200

__global__ void __launch_bounds__(256, 1) attn_tc_kernel(float* __restrict__ weights) {
    extern __shared__ char smem[];
    uint32_t sb = smem_u32(smem);
    int tid = threadIdx.x, lane = tid & 31, w = tid >> 5;
    int wm = (w >> 1) * 32;
    int wnS = (w & 1) * 64;    // S cols (key)
    int wnP = (w & 1) * 32;    // PV cols (d)
    int gid = lane >> 2, tid4 = lane & 3;
    int bh = blockIdx.y, q0 = blockIdx.x * 128;

    // persistent Q tile [128][64] hi/lo, pitch 72
    #pragma unroll
    for (int e = 0; e < 4; e++) {
        int i = tid + e * 256;
        int row = i >> 3, cc = i & 7;
        size_t g = ((size_t)bh * SEQ + q0 + row) * DH + cc * 8;
        int so = row * 144 + cc * 16;
        *(uint4*)(smem + AS_QH + so) = *(const uint4*)(g_QH + g);
        *(uint4*)(smem + AS_QL + so) = *(const uint4*)(g_QL + g);
    }

    float* wbase = weights + (size_t)bh * SEQ * SEQ;
    float pv[2][4][4] = {};
    float rsum[4] = {};

    for (int kt = 0; kt < SEQ / 128; kt++) {
        __syncthreads();
        // K tile [128][64] pitch 72; Vt tile [64][128] pitch 136
        #pragma unroll
        for (int e = 0; e < 4; e++) {
            int i = tid + e * 256;
            int row = i >> 3, cc = i & 7;
            size_t g = ((size_t)bh * SEQ + kt * 128 + row) * DH + cc * 8;
            int so = row * 144 + cc * 16;
            *(uint4*)(smem + AS_KH + so) = *(const uint4*)(g_KH + g);
            *(uint4*)(smem + AS_KL + so) = *(const uint4*)(g_KL + g);
        }
        #pragma unroll
        for (int e = 0; e < 4; e++) {
            int i = tid + e * 256;
            int row = i >> 4, cc = i & 15;
            size_t g = ((size_t)bh * DH + row) * SEQ + kt * 128 + cc * 8;
            int so = row * 272 + cc * 16;
            *(uint4*)(smem + AS_VH + so) = *(const uint4*)(g_VtH + g);
            *(uint4*)(smem + AS_VL + so) = *(const uint4*)(g_VtL + g);
        }
        __syncthreads();

        // ---- S = Q K^T (scale folded in Q), K=64 ----
        float s[2][8][4] = {};
        #pragma unroll
        for (int ks = 0; ks < 64; ks += 16) {
            uint32_t ah[2][4], al[2][4], bhf[8][2], blf[8][2];
            #pragma unroll
            for (int mt = 0; mt < 2; mt++) {
                uint32_t ad = sb + AS_QH + (uint32_t)(wm + mt * 16 + (lane & 15)) * 144
                            + (ks + (lane >> 4) * 8) * 2;
                ldsm4(ah[mt], ad);
                ldsm4(al[mt], ad + (AS_QL - AS_QH));
            }
            #pragma unroll
            for (int nt2 = 0; nt2 < 4; nt2++) {
                uint32_t bd = sb + AS_KH
                            + (uint32_t)(wnS + nt2 * 16 + ((lane >> 4) << 3) + (lane & 7)) * 144
                            + (ks + ((lane >> 3) & 1) * 8) * 2;
                uint32_t t[4];
                ldsm4(t, bd);
                bhf[nt2*2][0]=t[0]; bhf[nt2*2][1]=t[1]; bhf[nt2*2+1][0]=t[2]; bhf[nt2*2+1][1]=t[3];
                ldsm4(t, bd + (AS_KL - AS_KH));
                blf[nt2*2][0]=t[0]; blf[nt2*2][1]=t[1]; blf[nt2*2+1][0]=t[2]; blf[nt2*2+1][1]=t[3];
            }
            #pragma unroll
            for (int mt = 0; mt < 2; mt++)
                #pragma unroll
                for (int nt = 0; nt < 8; nt++) {
                    mma16816(s[mt][nt], ah[mt], bhf[nt]);
                    mma16816(s[mt][nt], ah[mt], blf[nt]);
                    mma16816(s[mt][nt], al[mt], bhf[nt]);
                }
        }

        // ---- exp, rowsum, weights gmem, E -> smem ----
        #pragma unroll
        for (int mt = 0; mt < 2; mt++)
            #pragma unroll
            for (int rh = 0; rh < 2; rh++) {
                int row = wm + mt * 16 + rh * 8 + gid;
                float rs = 0.f;
                #pragma unroll
                for (int nt = 0; nt < 8; nt++) {
                    float v0 = __expf(s[mt][nt][rh * 2 + 0]);
                    float v1 = __expf(s[mt][nt][rh * 2 + 1]);
                    rs += v0 + v1;
                    int col = wnS + nt * 8 + tid4 * 2;
                    *(float2*)&wbase[(size_t)(q0 + row) * SEQ + kt * 128 + col] =
                        make_float2(v0, v1);
                    __nv_bfloat16 h0, l0, h1, l1;
                    split2(v0, h0, l0); split2(v1, h1, l1);
                    *(uint32_t*)(smem + AS_EH + row * 272 + col * 2) = pack2(h0, h1);
                    *(uint32_t*)(smem + AS_EL + row * 272 + col * 2) = pack2(l0, l1);
                }
                rsum[mt * 2 + rh] += rs;
            }
        __syncthreads();

        // ---- pv += E Vt^T, K=128 ----
        #pragma unroll 2
        for (int ks = 0; ks < 8; ks++) {
            uint32_t eh[2][4], el[2][4], vh[4][2], vl[4][2];
            #pragma unroll
            for (int mt = 0; mt < 2; mt++) {
                uint32_t ad = sb + AS_EH + (uint32_t)(wm + mt * 16 + (lane & 15)) * 272
                            + (ks * 16 + (lane >> 4) * 8) * 2;
                ldsm4(eh[mt], ad);
                ldsm4(el[mt], ad + (AS_EL - AS_EH));
            }
            #pragma unroll
            for (int nt2 = 0; nt2 < 2; nt2++) {
                uint32_t bd = sb + AS_VH
                            + (uint32_t)(wnP + nt2 * 16 + ((lane >> 4) << 3) + (lane & 7)) * 272
                            + (ks * 16 + ((lane >> 3) & 1) * 8) * 2;
                uint32_t t[4];
                ldsm4(t, bd);
                vh[nt2*2][0]=t[0]; vh[nt2*2][1]=t[1]; vh[nt2*2+1][0]=t[2]; vh[nt2*2+1][1]=t[3];
                ldsm4(t, bd + (AS_VL - AS_VH));
                vl[nt2*2][0]=t[0]; vl[nt2*2][1]=t[1]; vl[nt2*2+1][0]=t[2]; vl[nt2*2+1][1]=t[3];
            }
            #pragma unroll
            for (int mt = 0; mt < 2; mt++)
                #pragma unroll
                for (int nt = 0; nt < 4; nt++) {
                    mma16816(pv[mt][nt], eh[mt], vh[nt]);
                    mma16816(pv[mt][nt], eh[mt], vl[nt]);
                    mma16816(pv[mt][nt], el[mt], vh[nt]);
                }
        }
    }

    // ---- final: rowsum reduce, rinv, attended store ----
    float* red = (float*)(smem + AS_RED);
    #pragma unroll
    for (int i = 0; i < 4; i++) {
        rsum[i] += __shfl_xor_sync(0xFFFFFFFFu, rsum[i], 1);
        rsum[i] += __shfl_xor_sync(0xFFFFFFFFu, rsum[i], 2);
    }
    __syncthreads();
    if (tid4 == 0) {
        #pragma unroll
        for (int i = 0; i < 4; i++) {
            int row = wm + (i >> 1) * 16 + (i & 1) * 8 + gid;
            red[row * 2 + (w & 1)] = rsum[i];
        }
    }
    __syncthreads();

    int b = bh >> 4, h = bh & 15;
    #pragma unroll
    for (int mt = 0; mt < 2; mt++)
        #pragma unroll
        for (int rh = 0; rh < 2; rh++) {
            int row = wm + mt * 16 + rh * 8 + gid;
            float ri = 1.0f / (red[row * 2] + red[row * 2 + 1]);
            if ((w & 1) == 0 && tid4 == 0)
                g_rinv[(size_t)bh * SEQ + q0 + row] = ri;
            #pragma unroll
            for (int nt = 0; nt < 4; nt++) {
                float v0 = pv[mt][nt][rh * 2 + 0] * ri;
                float v1 = pv[mt][nt][rh * 2 + 1] * ri;
                int d = wnP + nt * 8 + tid4 * 2;
                __nv_bfloat16 h0, l0, h1, l1;
                split2(v0, h0, l0); split2(v1, h1, l1);
                size_t dst = ((size_t)(b * SEQ + q0 + row)) * DM + h * DH + d;
                *(uint32_t*)&g_attH[dst] = pack2(h0, h1);
                *(uint32_t*)&g_attL[dst] = pack2(l0, l1);
            }
        }
}

// ---------------------------------------------------------------------------
// Normalize weights in place
// ---------------------------------------------------------------------------
__global__ void norm_kernel(float* __restrict__ w) {
    size_t f4 = (size_t)blockIdx.x * blockDim.x + threadIdx.x;
    size_t fidx = f4 * 4;
    int rowi = (int)(fidx >> 11);
    float r = g_rinv[rowi];
    float4 v = *(float4*)&w[fidx];
    v.x *= r; v.y *= r; v.z *= r; v.w *= r;
    *(float4*)&w[fidx] = v;
}

// ---------------------------------------------------------------------------
extern "C" void kernel_launch(void* const* d_in, const int* in_sizes, int n_in,
                              void* d_out, int out_size) {
    const float* x  = (const float*)d_in[0];
    const float* wq = (const float*)d_in[1];
    const float* bq = (const float*)d_in[2];
    const float* wk = (const float*)d_in[3];
    const float* bk = (const float*)d_in[4];
    const float* wv = (const float*)d_in[5];
    const float* bv = (const float*)d_in[6];
    const float* wo = (const float*)d_in[7];
    const float* bo = (const float*)d_in[8];

    float* out     = (float*)d_out;
    float* weights = out + (size_t)M_TOT * DM;

    cudaFuncSetAttribute(proj_qkv_kernel, cudaFuncAttributeMaxDynamicSharedMemorySize, PROJ_SMEM);
    cudaFuncSetAttribute(proj_o_kernel,   cudaFuncAttributeMaxDynamicSharedMemorySize, PROJ_SMEM);
    cudaFuncSetAttribute(attn_tc_kernel,  cudaFuncAttributeMaxDynamicSharedMemorySize, ATTN_SMEM);

    split_x_kernel<<<(M_TOT * DM / 4) / 256, 256>>>(x);
    dim3 tg(32, 32), tb(32, 8);
    tsplit_kernel<<<tg, tb>>>(wq, 0);
    tsplit_kernel<<<tg, tb>>>(wk, 1);
    tsplit_kernel<<<tg, tb>>>(wv, 2);
    tsplit_kernel<<<tg, tb>>>(wo, 3);

    proj_qkv_kernel<<<dim3(3 * DM / 128, M_TOT / 128), 256, PROJ_SMEM>>>(bq, bk, bv);

    attn_tc_kernel<<<dim3(SEQ / 128, BH_TOT), 256, ATTN_SMEM>>>(weights);

    size_t nf4 = (size_t)BH_TOT * SEQ * SEQ / 4;
    norm_kernel<<<(unsigned)(nf4 / 256), 256>>>(weights);

    proj_o_kernel<<<dim3(DM / 128, M_TOT / 128), 256, PROJ_SMEM>>>(bo, out);
}